// round 1
// baseline (speedup 1.0000x reference)
#include <cuda_runtime.h>
#include <cuda_bf16.h>

// Problem constants
#define B   256
#define T   1024
#define H   128
#define I   19
#define BT  (B*T)            // 262144
#define NEL (BT*H)           // 33554432

// Scratch (device globals: allocation-free per harness rules)
__device__ float g_buf0[NEL];   // pre-activations (layer0 then layer1)
__device__ float g_buf1[NEL];   // layer-0 hidden outputs

typedef unsigned long long u64;

__device__ __forceinline__ u64 fma2(u64 a, u64 b, u64 c) {
    u64 d;
    asm("fma.rn.f32x2 %0, %1, %2, %3;" : "=l"(d) : "l"(a), "l"(b), "l"(c));
    return d;
}
__device__ __forceinline__ u64 add2(u64 a, u64 b) {
    u64 d;
    asm("add.rn.f32x2 %0, %1, %2;" : "=l"(d) : "l"(a), "l"(b));
    return d;
}
__device__ __forceinline__ float red2(u64 a) {
    float x, y;
    asm("mov.b64 {%0, %1}, %2;" : "=f"(x), "=f"(y) : "l"(a));
    return x + y;
}

// tanh(x) = 1 - 2/(1 + e^{2x}); ex2/rcp approx are ~2 ulp -> ~1e-7 abs err.
__device__ __forceinline__ float fast_tanh(float x) {
    float e, r;
    asm("ex2.approx.f32 %0, %1;" : "=f"(e) : "f"(x * 2.8853900817779268f));
    asm("rcp.approx.f32 %0, %1;" : "=f"(r) : "f"(e + 1.0f));
    return fmaf(-2.0f, r, 1.0f);
}

// ---------------------------------------------------------------------------
// Kernel 1: pre0[bt, j] = x[bt, :19] . W_ih0[j, :19] + b_ih0[j] + b_hh0[j]
// One thread per output element. Memory-bound on the 134MB write.
// ---------------------------------------------------------------------------
__global__ void pre0_kernel(const float* __restrict__ x,
                            const float* __restrict__ W,
                            const float* __restrict__ bi,
                            const float* __restrict__ bh) {
    int idx = blockIdx.x * 256 + threadIdx.x;
    int j  = idx & (H - 1);
    int bt = idx >> 7;
    const float* xr = x + bt * I;
    const float* wr = W + j * I;
    float acc = __ldg(bi + j) + __ldg(bh + j);
#pragma unroll
    for (int f = 0; f < I; f++)
        acc = fmaf(__ldg(xr + f), __ldg(wr + f), acc);
    g_buf0[idx] = acc;
}

// ---------------------------------------------------------------------------
// Kernel 2: recurrent scan. One CTA per batch row, 128 threads (thread j =
// output unit j). W_hh row j lives in 64 packed f32x2 registers. h double-
// buffered in shared; one __syncthreads per step. layer==0: g_buf0 -> g_buf1;
// layer==1: g_buf0 -> dout.
// ---------------------------------------------------------------------------
__global__ void __launch_bounds__(128, 2)
scan_kernel(int layer, const float* __restrict__ W, float* __restrict__ dout) {
    __shared__ __align__(16) float hbuf[2][H];
    const int j = threadIdx.x;
    const int b = blockIdx.x;

    const float* __restrict__ pre = g_buf0;
    float* __restrict__ out = (layer == 0) ? g_buf1 : dout;

    // Load W_hh row j as 64 packed f32x2 pairs (over k).
    u64 wp[64];
    const u64* wrow = reinterpret_cast<const u64*>(W + j * H);
#pragma unroll
    for (int i = 0; i < 64; i++) wp[i] = __ldg(wrow + i);

    hbuf[0][j] = 0.0f;
    __syncthreads();

    const int base = b * (T * H) + j;
    float p = __ldg(pre + base);

#pragma unroll 1
    for (int t = 0; t < T; t++) {
        // prefetch next timestep's pre-activation
        int tn = (t + 1 < T) ? (t + 1) : (T - 1);
        float pn = __ldg(pre + base + tn * H);

        const ulonglong2* hp = reinterpret_cast<const ulonglong2*>(hbuf[t & 1]);
        u64 a0 = 0, a1 = 0, a2 = 0, a3 = 0;
#pragma unroll
        for (int i = 0; i < 32; i += 2) {
            ulonglong2 h0 = hp[i];
            ulonglong2 h1 = hp[i + 1];
            a0 = fma2(wp[2 * i + 0], h0.x, a0);
            a1 = fma2(wp[2 * i + 1], h0.y, a1);
            a2 = fma2(wp[2 * i + 2], h1.x, a2);
            a3 = fma2(wp[2 * i + 3], h1.y, a3);
        }
        float s = p + red2(add2(add2(a0, a1), add2(a2, a3)));
        float h = fast_tanh(s);

        hbuf[(t & 1) ^ 1][j] = h;
        out[base + t * H] = h;
        p = pn;
        __syncthreads();
    }
}

// ---------------------------------------------------------------------------
// Kernel 3: layer-1 input projection (bulk GEMM, fully parallel):
// g_buf0[r, j] = g_buf1[r, :] . W_ih1[j, :] + b_ih1[j] + b_hh1[j]
// Same register-resident-W trick; 2 rows per iteration to amortize barriers.
// ---------------------------------------------------------------------------
#define PROJ_BLOCKS 512
#define PROJ_ROWS   (BT / PROJ_BLOCKS)   // 512 rows per block

__global__ void __launch_bounds__(128, 2)
proj_kernel(const float* __restrict__ W,
            const float* __restrict__ bi,
            const float* __restrict__ bh) {
    __shared__ __align__(16) float r0s[H];
    __shared__ __align__(16) float r1s[H];
    const int j = threadIdx.x;

    u64 wp[64];
    const u64* wrow = reinterpret_cast<const u64*>(W + j * H);
#pragma unroll
    for (int i = 0; i < 64; i++) wp[i] = __ldg(wrow + i);

    const float bias = __ldg(bi + j) + __ldg(bh + j);
    const int rbeg = blockIdx.x * PROJ_ROWS;

#pragma unroll 1
    for (int r = rbeg; r < rbeg + PROJ_ROWS; r += 2) {
        r0s[j] = g_buf1[r * H + j];
        r1s[j] = g_buf1[r * H + H + j];
        __syncthreads();

        const ulonglong2* h0p = reinterpret_cast<const ulonglong2*>(r0s);
        const ulonglong2* h1p = reinterpret_cast<const ulonglong2*>(r1s);
        u64 a0 = 0, a1 = 0, c0 = 0, c1 = 0;
#pragma unroll
        for (int i = 0; i < 32; i++) {
            ulonglong2 x0 = h0p[i];
            ulonglong2 x1 = h1p[i];
            a0 = fma2(wp[2 * i + 0], x0.x, a0);
            a1 = fma2(wp[2 * i + 1], x0.y, a1);
            c0 = fma2(wp[2 * i + 0], x1.x, c0);
            c1 = fma2(wp[2 * i + 1], x1.y, c1);
        }
        g_buf0[r * H + j]     = bias + red2(add2(a0, a1));
        g_buf0[r * H + H + j] = bias + red2(add2(c0, c1));
        __syncthreads();
    }
}

// ---------------------------------------------------------------------------
extern "C" void kernel_launch(void* const* d_in, const int* in_sizes, int n_in,
                              void* d_out, int out_size) {
    const float* x     = (const float*)d_in[0];
    const float* W_ih0 = (const float*)d_in[1];
    const float* W_hh0 = (const float*)d_in[2];
    const float* b_ih0 = (const float*)d_in[3];
    const float* b_hh0 = (const float*)d_in[4];
    const float* W_ih1 = (const float*)d_in[5];
    const float* W_hh1 = (const float*)d_in[6];
    const float* b_ih1 = (const float*)d_in[7];
    const float* b_hh1 = (const float*)d_in[8];
    float* out = (float*)d_out;

    // Layer 0 input projection -> g_buf0
    pre0_kernel<<<NEL / 256, 256>>>(x, W_ih0, b_ih0, b_hh0);
    // Layer 0 scan: g_buf0 -> g_buf1
    scan_kernel<<<B, 128>>>(0, W_hh0, out);
    // Layer 1 input projection: g_buf1 -> g_buf0
    proj_kernel<<<PROJ_BLOCKS, 128>>>(W_ih1, b_ih1, b_hh1);
    // Layer 1 scan: g_buf0 -> out
    scan_kernel<<<B, 128>>>(1, W_hh1, out);
}